// round 11
// baseline (speedup 1.0000x reference)
#include <cuda_runtime.h>

// Shapes (fixed):
//   points          (B, N, 3)  f32
//   point_features  (B, N, C)  f32
//   boxes3d         (B, M, 7)  f32  (cx, cy, cz_bottom, dx, dy, dz, rz)
// Output d_out:
//   pooled_features (B, M, S, 3+C) f32   [+ pooled_empty_flag (B,M) at tail if room]
#define BB    4
#define NPTS  16384
#define MBOX  128
#define CFEAT 128
#define SSAMP 512
#define ROW   (3 + CFEAT)        // 131
#define NBOX  (BB * MBOX)        // 512
#define NSEG  16                 // segments per box
#define SEGPTS (NPTS / NSEG)     // 1024 points per segment
#define BOXG  4                  // boxes per scan CTA

// Cross-kernel scratch (device globals — no allocation).
// Per (box, segment): ordered in-box indices (first 512 suffice: global rank
// j < S=512 implies local rank <= j < 512).
__device__ int g_seg_idx[NBOX * NSEG * SSAMP];   // 16 MB
__device__ int g_scnt[NBOX * NSEG];

// ============================ Kernel 1: segmented scan ============================
// One CTA per (box-group-of-4, segment): stage 1024 points once, test 4 boxes.
__global__ __launch_bounds__(256)
void scan_kernel(const float* __restrict__ points,
                 const float* __restrict__ boxes)
{
    __shared__ float s_pts[SEGPTS * 3];    // 12 KB staged points
    __shared__ int   s_wcnt[32];           // per (chunk, warp) counts, chunk-major

    const int gid  = blockIdx.x;           // ((b*32 + grp) << 4) | seg
    const int seg  = gid & 15;
    const int grp  = (gid >> 4) & 31;
    const int b    = gid >> 9;
    const int box0 = b * MBOX + grp * BOXG;
    const int tid  = threadIdx.x;
    const int wid  = tid >> 5;
    const int lane = tid & 31;

    // --- stage 1024 points: 768 coalesced float4 loads ---
    const float* pts = points + (size_t)b * NPTS * 3 + (size_t)seg * SEGPTS * 3;
    {
        const float4* src4 = reinterpret_cast<const float4*>(pts);
        float4* dst4 = reinterpret_cast<float4*>(s_pts);
        #pragma unroll
        for (int i = 0; i < 3; i++) dst4[tid + i * 256] = src4[tid + i * 256];
    }
    __syncthreads();

    for (int bxi = 0; bxi < BOXG; bxi++) {
        const int box_id = box0 + bxi;
        const float* bx = boxes + box_id * 7;
        const float cx  = bx[0];
        const float cy  = bx[1];
        const float dxh = 0.5f * bx[3];
        const float dyh = 0.5f * bx[4];
        const float dzh = 0.5f * bx[5];
        const float cz  = bx[2] + dzh;
        const float rz  = bx[6];
        const float cosa = cosf(-rz);      // replicate reference op order
        const float sina = sinf(-rz);

        // --- test 4 chunks of 256, one ballot each ---
        unsigned bal[4];
        #pragma unroll
        for (int k = 0; k < 4; k++) {
            const int p  = k * 256 + tid;
            const float px = s_pts[p * 3 + 0];
            const float py = s_pts[p * 3 + 1];
            const float pz = s_pts[p * 3 + 2];
            const float sx = px - cx;
            const float sy = py - cy;
            const float lx = sx * cosa - sy * sina;
            const float ly = sx * sina + sy * cosa;
            const bool in =
                (fabsf(pz - cz) <= dzh) &&
                (lx > -dxh) && (lx < dxh) &&
                (ly > -dyh) && (ly < dyh);
            bal[k] = __ballot_sync(0xffffffffu, in);
            if (lane == 0) s_wcnt[k * 8 + wid] = __popc(bal[k]);
        }
        __syncthreads();

        // --- ordered prefix over the 32 (chunk, warp) groups ---
        int base_k[4];
        int total = 0;
        #pragma unroll
        for (int j = 0; j < 32; j++) {
            const int c = s_wcnt[j];
            #pragma unroll
            for (int k = 0; k < 4; k++)
                if (j == k * 8 + wid) base_k[k] = total;
            total += c;
        }
        // --- emit ordered global point indices for this (box, seg) ---
        int* my_idx = g_seg_idx + (box_id * NSEG + seg) * SSAMP;
        #pragma unroll
        for (int k = 0; k < 4; k++) {
            if ((bal[k] >> lane) & 1u) {
                const int pos = base_k[k] + __popc(bal[k] & ((1u << lane) - 1u));
                if (pos < SSAMP) my_idx[pos] = seg * SEGPTS + k * 256 + tid;
            }
        }
        if (tid == 0) g_scnt[box_id * NSEG + seg] = total;
        __syncthreads();                   // protect s_wcnt for next box
    }
}

// ============================ Kernel 2: gather + write ============================
// One CTA per (box, quarter): 128 output rows = 16768 floats, written as a flat
// aligned STG.128 stream. No smem staging, no barriers in the main loop.
__global__ __launch_bounds__(256)
void gather_kernel(const float* __restrict__ points,
                   const float* __restrict__ feats,
                   float* __restrict__ out,
                   float* __restrict__ flags)
{
    __shared__ int s_rowidx[128];          // resolved point index per output row
    __shared__ int s_cnt;

    const int box_id = blockIdx.x >> 2;
    const int q      = blockIdx.x & 3;
    const int b      = box_id / MBOX;
    const int tid    = threadIdx.x;

    // --- prologue: resolve indices once per row (threads 0..127) ---
    if (tid < 128) {
        const int* sc = g_scnt + box_id * NSEG;
        int pre[NSEG + 1];
        pre[0] = 0;
        #pragma unroll
        for (int k = 0; k < NSEG; k++) pre[k + 1] = pre[k] + sc[k];
        int cnt = pre[NSEG];
        if (cnt > SSAMP) cnt = SSAMP;
        if (tid == 0) s_cnt = cnt;
        if (cnt > 0) {
            const int s = q * 128 + tid;
            const int j = s % cnt;                 // global in-box rank (< 512)
            int k = 0;
            #pragma unroll
            for (int kk = 1; kk < NSEG; kk++)
                if (j >= pre[kk]) k = kk;
            s_rowidx[tid] = g_seg_idx[(box_id * NSEG + k) * SSAMP + (j - pre[k])];
        }
    }
    __syncthreads();
    const int cnt = s_cnt;

    float* oq = out + (size_t)box_id * (SSAMP * ROW) + q * 128 * ROW;  // 16B-aligned
    float4* o4 = reinterpret_cast<float4*>(oq);

    if (cnt == 0) {
        const float4 z = make_float4(0.f, 0.f, 0.f, 0.f);
        for (int i = tid; i < 4192; i += 256) __stcs(&o4[i], z);
        if (q == 0 && tid == 0 && flags != nullptr) flags[box_id] = 1.0f;
        return;
    }

    const float* pts = points + (size_t)b * NPTS * 3;
    const float* fb  = feats  + (size_t)b * NPTS * CFEAT;

    // Flat sweep: 4192 float4 per CTA, 16.4 per thread, all independent.
    #pragma unroll 4
    for (int i = tid; i < 4192; i += 256) {
        float v[4];
        #pragma unroll
        for (int e = 0; e < 4; e++) {
            const int f   = 4 * i + e;             // flat offset in quarter
            const int s   = f / ROW;               // local row 0..127 (mulhi)
            const int c   = f - s * ROW;           // column 0..130
            const int idx = s_rowidx[s];           // smem broadcast
            v[e] = (c < 3) ? pts[idx * 3 + c]
                           : __ldg(fb + (size_t)idx * CFEAT + (c - 3));
        }
        __stcs(&o4[i], make_float4(v[0], v[1], v[2], v[3]));
    }
    if (q == 0 && tid == 0 && flags != nullptr) flags[box_id] = 0.0f;
}

extern "C" void kernel_launch(void* const* d_in, const int* in_sizes, int n_in,
                              void* d_out, int out_size)
{
    const float* points = (const float*)d_in[0];   // (B, N, 3)
    const float* feats  = (const float*)d_in[1];   // (B, N, C)
    const float* boxes  = (const float*)d_in[2];   // (B, M, 7)

    float* out = (float*)d_out;
    const size_t feat_elems = (size_t)NBOX * SSAMP * ROW;   // 34,340,864
    float* flags = nullptr;
    if ((size_t)out_size >= feat_elems + (size_t)NBOX)
        flags = out + feat_elems;

    scan_kernel<<<(NBOX / BOXG) * NSEG, 256>>>(points, boxes);
    gather_kernel<<<NBOX * 4, 256>>>(points, feats, out, flags);
}

// round 12
// speedup vs baseline: 1.2920x; 1.2920x over previous
#include <cuda_runtime.h>

// Shapes (fixed):
//   points          (B, N, 3)  f32
//   point_features  (B, N, C)  f32
//   boxes3d         (B, M, 7)  f32  (cx, cy, cz_bottom, dx, dy, dz, rz)
// Output d_out:
//   pooled_features (B, M, S, 3+C) f32   [+ pooled_empty_flag (B,M) at tail if room]
#define BB    4
#define NPTS  16384
#define MBOX  128
#define CFEAT 128
#define SSAMP 512
#define ROW   (3 + CFEAT)        // 131
#define NBOX  (BB * MBOX)        // 512
#define NSEG  16                 // segments per box
#define SEGPTS (NPTS / NSEG)     // 1024 points per segment
#define BOXG  4                  // boxes per scan CTA

// Cross-kernel scratch (device globals — no allocation).
// Per (box, segment): ordered in-box indices (512 slots suffice: global rank
// j < S=512 implies local rank <= j < 512).
__device__ int g_seg_idx[NBOX * NSEG * SSAMP];   // 16 MB
__device__ int g_scnt[NBOX * NSEG];

// ============================ Kernel 1: segmented scan ============================
// One CTA per (box-group-of-4, segment). Points live in registers (4/thread),
// ordered compaction via per-thread mask + shfl warp scan. 1 barrier per box.
__global__ __launch_bounds__(256)
void scan_kernel(const float* __restrict__ points,
                 const float* __restrict__ boxes)
{
    __shared__ int s_wcnt[2][8];           // double-buffered per-warp counts

    const int gid  = blockIdx.x;           // ((b*32 + grp) << 4) | seg
    const int seg  = gid & 15;
    const int grp  = (gid >> 4) & 31;
    const int b    = gid >> 9;
    const int box0 = b * MBOX + grp * BOXG;
    const int tid  = threadIdx.x;
    const int wid  = tid >> 5;
    const int lane = tid & 31;

    // --- load this thread's 4 points (floats 12t..12t+11, 16B-aligned) ---
    const float4* src4 = reinterpret_cast<const float4*>(
        points + (size_t)b * NPTS * 3 + (size_t)seg * SEGPTS * 3);
    const float4 v0 = src4[3 * tid + 0];
    const float4 v1 = src4[3 * tid + 1];
    const float4 v2 = src4[3 * tid + 2];
    const float px[4] = { v0.x, v0.w, v1.z, v2.y };
    const float py[4] = { v0.y, v1.x, v1.w, v2.z };
    const float pz[4] = { v0.z, v1.y, v2.x, v2.w };

    int pb = 0;
    for (int bxi = 0; bxi < BOXG; bxi++) {
        const int box_id = box0 + bxi;
        const float* bx = boxes + box_id * 7;
        const float cx  = bx[0];
        const float cy  = bx[1];
        const float dxh = 0.5f * bx[3];
        const float dyh = 0.5f * bx[4];
        const float dzh = 0.5f * bx[5];
        const float cz  = bx[2] + dzh;
        const float rz  = bx[6];
        const float cosa = cosf(-rz);      // replicate reference op order
        const float sina = sinf(-rz);

        // --- membership mask for this thread's 4 consecutive points ---
        unsigned m = 0;
        #pragma unroll
        for (int e = 0; e < 4; e++) {
            const float sx = px[e] - cx;
            const float sy = py[e] - cy;
            const float lx = sx * cosa - sy * sina;
            const float ly = sx * sina + sy * cosa;
            const bool in =
                (fabsf(pz[e] - cz) <= dzh) &&
                (lx > -dxh) && (lx < dxh) &&
                (ly > -dyh) && (ly < dyh);
            m |= (unsigned)in << e;
        }
        const int c = __popc(m);

        // --- warp inclusive scan of per-thread counts ---
        int sc = c;
        #pragma unroll
        for (int off = 1; off < 32; off <<= 1) {
            const int n = __shfl_up_sync(0xffffffffu, sc, off);
            if (lane >= off) sc += n;
        }
        if (lane == 31) s_wcnt[pb][wid] = sc;
        __syncthreads();

        // --- block prefix over 8 warp totals ---
        int wbase = 0, total = 0;
        #pragma unroll
        for (int w = 0; w < 8; w++) {
            const int x = s_wcnt[pb][w];
            if (w < wid) wbase += x;
            total += x;
        }
        const int base = wbase + (sc - c);   // ordered: (wid, lane, e)

        // --- emit ordered global point indices ---
        int* my_idx = g_seg_idx + (box_id * NSEG + seg) * SSAMP;
        #pragma unroll
        for (int e = 0; e < 4; e++) {
            if ((m >> e) & 1u) {
                const int pos = base + __popc(m & ((1u << e) - 1u));
                if (pos < SSAMP) my_idx[pos] = seg * SEGPTS + 4 * tid + e;
            }
        }
        if (tid == 0) g_scnt[box_id * NSEG + seg] = total;
        pb ^= 1;                             // next box uses other s_wcnt buffer
    }
}

// ============================ Kernel 2: gather + write ============================
// One CTA per (box, quarter): 128 rows. Double-buffered 16-row smem tiles:
// gather of tile t+1 overlaps sweep of tile t; one barrier per tile.
__global__ __launch_bounds__(256)
void gather_kernel(const float* __restrict__ points,
                   const float* __restrict__ feats,
                   float* __restrict__ out,
                   float* __restrict__ flags)
{
    __shared__ float s_tile[2][16 * ROW];  // 2 x 8384 B
    __shared__ int   s_rowidx[128];
    __shared__ int   s_cnt;

    const int box_id = blockIdx.x >> 2;
    const int q      = blockIdx.x & 3;
    const int b      = box_id / MBOX;
    const int tid    = threadIdx.x;
    const int wid    = tid >> 5;
    const int lane   = tid & 31;

    // --- prologue: resolve indices once per row (threads 0..127) ---
    if (tid < 128) {
        const int* sc = g_scnt + box_id * NSEG;
        int pre[NSEG + 1];
        pre[0] = 0;
        #pragma unroll
        for (int k = 0; k < NSEG; k++) pre[k + 1] = pre[k] + sc[k];
        int cnt = pre[NSEG];
        if (cnt > SSAMP) cnt = SSAMP;
        if (tid == 0) s_cnt = cnt;
        if (cnt > 0) {
            const int s = q * 128 + tid;
            const int j = s % cnt;                 // global in-box rank (< 512)
            int k = 0;
            #pragma unroll
            for (int kk = 1; kk < NSEG; kk++)
                if (j >= pre[kk]) k = kk;
            s_rowidx[tid] = g_seg_idx[(box_id * NSEG + k) * SSAMP + (j - pre[k])];
        }
    }
    __syncthreads();
    const int cnt = s_cnt;

    float* oq = out + (size_t)box_id * (SSAMP * ROW) + q * 128 * ROW;  // 16B-aligned
    if (cnt == 0) {
        const float4 z = make_float4(0.f, 0.f, 0.f, 0.f);
        float4* o4 = reinterpret_cast<float4*>(oq);
        for (int i = tid; i < 4192; i += 256) __stcs(&o4[i], z);
        if (q == 0 && tid == 0 && flags != nullptr) flags[box_id] = 1.0f;
        return;
    }

    const float* pts = points + (size_t)b * NPTS * 3;
    const float* fb  = feats  + (size_t)b * NPTS * CFEAT;

    // gather 16 rows of tile t into buf: warp w handles rows w*2, w*2+1
    auto gather_tile = [&](int t, float* buf) {
        #pragma unroll
        for (int i = 0; i < 2; i++) {
            const int r   = wid * 2 + i;
            const int idx = s_rowidx[t * 16 + r];
            const float* frow = fb + (size_t)idx * CFEAT;
            float* srow = buf + r * ROW;
            #pragma unroll
            for (int p = 0; p < 4; p++)             // bank (3r+3+lane)%32: conflict-free
                srow[3 + 32 * p + lane] = frow[32 * p + lane];
            if (lane < 3) srow[lane] = pts[idx * 3 + lane];
        }
    };

    gather_tile(0, s_tile[0]);
    __syncthreads();
    #pragma unroll
    for (int t = 0; t < 8; t++) {
        if (t < 7) gather_tile(t + 1, s_tile[(t + 1) & 1]);   // overlaps sweep below
        // sweep tile t: 2096 floats = 524 aligned float4 streaming stores
        const float4* s4 = reinterpret_cast<const float4*>(s_tile[t & 1]);
        float4* o4 = reinterpret_cast<float4*>(oq + t * 16 * ROW);
        for (int i = tid; i < 524; i += 256) __stcs(&o4[i], s4[i]);
        __syncthreads();                    // both gather(t+1) and sweep(t) done
    }
    if (q == 0 && tid == 0 && flags != nullptr) flags[box_id] = 0.0f;
}

extern "C" void kernel_launch(void* const* d_in, const int* in_sizes, int n_in,
                              void* d_out, int out_size)
{
    const float* points = (const float*)d_in[0];   // (B, N, 3)
    const float* feats  = (const float*)d_in[1];   // (B, N, C)
    const float* boxes  = (const float*)d_in[2];   // (B, M, 7)

    float* out = (float*)d_out;
    const size_t feat_elems = (size_t)NBOX * SSAMP * ROW;   // 34,340,864
    float* flags = nullptr;
    if ((size_t)out_size >= feat_elems + (size_t)NBOX)
        flags = out + feat_elems;

    scan_kernel<<<(NBOX / BOXG) * NSEG, 256>>>(points, boxes);
    gather_kernel<<<NBOX * 4, 256>>>(points, feats, out, flags);
}